// round 12
// baseline (speedup 1.0000x reference)
#include <cuda_runtime.h>
#include <cuda_bf16.h>
#include <cstdint>

#define S 2048
#define HID 2048
#define NH 16
#define HD 128
#define BATCH 2
#define MROWS (BATCH*S)   // 4096

typedef unsigned long long ull;
typedef __nv_bfloat16 bf16;

// ---------------- scratch (static device allocations; no cudaMalloc) --------
__device__ float g_V [(size_t)MROWS*HID];
__device__ float g_Sc[(size_t)BATCH*NH*S*S];   // raw scores -> p (536 MB)
__device__ float g_m [BATCH*NH*S];
__device__ float g_li[BATCH*NH*S];
__device__ float g_pm[(size_t)BATCH*NH*S*16];  // per-(row, ktile) partial max
__device__ float g_pl[(size_t)BATCH*NH*S*16];  // per-(row, ktile) partial sumexp

__device__ bf16 g_hA[(size_t)MROWS*HID];       // GEMM A operand (hi)
__device__ bf16 g_lA[(size_t)MROWS*HID];       // GEMM A operand (lo)
__device__ bf16 g_hW[(size_t)HID*HID];
__device__ bf16 g_lW[(size_t)HID*HID];
__device__ bf16 g_hQs[(size_t)MROWS*HID];      // Q projection, split
__device__ bf16 g_lQs[(size_t)MROWS*HID];
__device__ bf16 g_hKs[(size_t)MROWS*HID];      // K projection, split
__device__ bf16 g_lKs[(size_t)MROWS*HID];
__device__ bf16 g_hVt[(size_t)HID*MROWS];      // V^T, split  [HID x MROWS]
__device__ bf16 g_lVt[(size_t)HID*MROWS];

// ======================= PTX helpers =========================================
__device__ __forceinline__ uint32_t smem_u32(const void* p){
    uint32_t a;
    asm("{ .reg .u64 t; cvta.to.shared.u64 t, %1; cvt.u32.u64 %0, t; }" : "=r"(a) : "l"(p));
    return a;
}
#define CP16(sm, gp)  asm volatile("cp.async.cg.shared.global [%0], [%1], 16;" :: "r"(sm), "l"(gp) : "memory")
#define CP_COMMIT()   asm volatile("cp.async.commit_group;" ::: "memory")
#define CP_WAIT1()    asm volatile("cp.async.wait_group 1;" ::: "memory")
#define CP_WAIT0()    asm volatile("cp.async.wait_group 0;" ::: "memory")

#define LDSM4(R, A) asm volatile("ldmatrix.sync.aligned.m8n8.x4.shared.b16 {%0,%1,%2,%3}, [%4];" \
    : "=r"((R)[0]), "=r"((R)[1]), "=r"((R)[2]), "=r"((R)[3]) : "r"(A))
#define LDSM2(R, A) asm volatile("ldmatrix.sync.aligned.m8n8.x2.shared.b16 {%0,%1}, [%2];" \
    : "=r"((R)[0]), "=r"((R)[1]) : "r"(A))

#define MMA16816(D, Af, Bf) asm volatile( \
    "mma.sync.aligned.m16n8k16.row.col.f32.bf16.bf16.f32 " \
    "{%0,%1,%2,%3}, {%4,%5,%6,%7}, {%8,%9}, {%0,%1,%2,%3};" \
    : "+f"((D)[0]), "+f"((D)[1]), "+f"((D)[2]), "+f"((D)[3]) \
    : "r"((Af)[0]), "r"((Af)[1]), "r"((Af)[2]), "r"((Af)[3]), \
      "r"((Bf)[0]), "r"((Bf)[1]))

__device__ __forceinline__ uint32_t pack_bf2(float a, float b){
    return (uint32_t)__bfloat16_as_ushort(__float2bfloat16(a))
         | ((uint32_t)__bfloat16_as_ushort(__float2bfloat16(b)) << 16);
}

// ======================= prep kernels ========================================
__global__ void __launch_bounds__(256) split_hi_lo(
    const float* __restrict__ in, bf16* __restrict__ hi,
    bf16* __restrict__ lo, int n4)
{
    int i = blockIdx.x * 256 + threadIdx.x;
    if (i >= n4) return;
    float4 v = ((const float4*)in)[i];
    float vv[4] = {v.x, v.y, v.z, v.w};
    unsigned short hb[4], lb[4];
#pragma unroll
    for (int j = 0; j < 4; j++) {
        bf16 h = __float2bfloat16(vv[j]);
        float r = vv[j] - __bfloat162float(h);
        hb[j] = __bfloat16_as_ushort(h);
        lb[j] = __bfloat16_as_ushort(__float2bfloat16(r));
    }
    ull hv = (ull)hb[0] | ((ull)hb[1] << 16) | ((ull)hb[2] << 32) | ((ull)hb[3] << 48);
    ull lv = (ull)lb[0] | ((ull)lb[1] << 16) | ((ull)lb[2] << 32) | ((ull)lb[3] << 48);
    ((ull*)hi)[i] = hv;
    ((ull*)lo)[i] = lv;
}

// in [RI x CI] fp32 -> out [CI x RI] bf16 hi/lo (transpose + split)
__global__ void __launch_bounds__(256) transpose_split(
    const float* __restrict__ in, bf16* __restrict__ hiT,
    bf16* __restrict__ loT, int CI, int RI)
{
    __shared__ float ts[32][33];
    int tx = threadIdx.x, ty = threadIdx.y;          // block (32,8)
    int n0 = blockIdx.x * 32, k0 = blockIdx.y * 32;
#pragma unroll
    for (int j = 0; j < 4; j++)
        ts[ty + j * 8][tx] = in[(size_t)(k0 + ty + j * 8) * CI + n0 + tx];
    __syncthreads();
#pragma unroll
    for (int j = 0; j < 4; j++) {
        float v = ts[tx][ty + j * 8];                // = in[k0+tx][n0+ty+j*8]
        bf16 h = __float2bfloat16(v);
        bf16 l = __float2bfloat16(v - __bfloat162float(h));
        size_t oi = (size_t)(n0 + ty + j * 8) * RI + k0 + tx;
        hiT[oi] = h;
        loT[oi] = l;
    }
}

// ======================= HMMA GEMM: C = A@W + bias ===========================
#define BK 32
#define NKCH (HID/BK)                 // 64
#define SSTR 40                       // bf16 per smem row (pad 32->40)
#define MATB (128*SSTR*2)             // 10240 B per matrix tile
#define STAGEB (4*MATB)               // 40960 B
#define GSMEM (2*STAGEB)              // 81920 B
#define AVSMEM (GSMEM + 1024)

__global__ void __launch_bounds__(256) gemm_hmma(
    const bf16* __restrict__ Ahi, const bf16* __restrict__ Alo,
    const bf16* __restrict__ Bhi, const bf16* __restrict__ Blo,
    const float* __restrict__ bias, float* __restrict__ C,
    bf16* __restrict__ Ch, bf16* __restrict__ Cl)
{
    extern __shared__ __align__(128) char smg[];
    uint32_t sb = smem_u32(smg);
    int tid = threadIdx.x, lane = tid & 31, wid = tid >> 5;
    int brow = blockIdx.y * 128, bcol = blockIdx.x * 128;
    int wm = (wid >> 1) * 32, wn = (wid & 1) * 64;

    int lr = tid >> 2, lc = (tid & 3) * 8;
    const bf16* srcA0h = Ahi + (size_t)(brow + lr) * HID + lc;
    const bf16* srcA1h = Ahi + (size_t)(brow + lr + 64) * HID + lc;
    const bf16* srcA0l = Alo + (size_t)(brow + lr) * HID + lc;
    const bf16* srcA1l = Alo + (size_t)(brow + lr + 64) * HID + lc;
    const bf16* srcB0h = Bhi + (size_t)(bcol + lr) * HID + lc;
    const bf16* srcB1h = Bhi + (size_t)(bcol + lr + 64) * HID + lc;
    const bf16* srcB0l = Blo + (size_t)(bcol + lr) * HID + lc;
    const bf16* srcB1l = Blo + (size_t)(bcol + lr + 64) * HID + lc;
    uint32_t d0 = (uint32_t)(lr * SSTR + lc) * 2;
    uint32_t d1 = (uint32_t)((lr + 64) * SSTR + lc) * 2;

#define LOAD_CHUNK(kk, st) do { \
    uint32_t bb = sb + (uint32_t)(st) * STAGEB; \
    int k0 = (kk) * BK; \
    CP16(bb + 0*MATB + d0, srcA0h + k0); CP16(bb + 0*MATB + d1, srcA1h + k0); \
    CP16(bb + 1*MATB + d0, srcA0l + k0); CP16(bb + 1*MATB + d1, srcA1l + k0); \
    CP16(bb + 2*MATB + d0, srcB0h + k0); CP16(bb + 2*MATB + d1, srcB1h + k0); \
    CP16(bb + 3*MATB + d0, srcB0l + k0); CP16(bb + 3*MATB + d1, srcB1l + k0); \
    CP_COMMIT(); } while (0)

    uint32_t a_off = (uint32_t)((wm + (lane & 15)) * SSTR + ((lane >> 1) & 8)) * 2;
    uint32_t b_off = (uint32_t)((wn + (lane & 7)) * SSTR + (lane & 8)) * 2;

    float acc[2][8][4];
#pragma unroll
    for (int mt = 0; mt < 2; mt++)
#pragma unroll
        for (int nt = 0; nt < 8; nt++)
#pragma unroll
            for (int j = 0; j < 4; j++) acc[mt][nt][j] = 0.0f;

    LOAD_CHUNK(0, 0);
    LOAD_CHUNK(1, 1);

    for (int k = 0; k < NKCH; k++) {
        if (k < NKCH - 2) { CP_WAIT1(); } else { CP_WAIT0(); }
        __syncthreads();
        uint32_t stb = sb + (uint32_t)(k & 1) * STAGEB;
#pragma unroll
        for (int kst = 0; kst < 2; kst++) {
            uint32_t kb = (uint32_t)kst * 32;
            uint32_t ah[2][4], al[2][4];
            LDSM4(ah[0], stb + 0*MATB + a_off + kb);
            LDSM4(ah[1], stb + 0*MATB + a_off + kb + 16*SSTR*2);
            LDSM4(al[0], stb + 1*MATB + a_off + kb);
            LDSM4(al[1], stb + 1*MATB + a_off + kb + 16*SSTR*2);
            uint32_t bh[8][2], bl[8][2];
#pragma unroll
            for (int nt = 0; nt < 8; nt++) {
                LDSM2(bh[nt], stb + 2*MATB + b_off + kb + nt*8*SSTR*2);
                LDSM2(bl[nt], stb + 3*MATB + b_off + kb + nt*8*SSTR*2);
            }
#pragma unroll
            for (int mt = 0; mt < 2; mt++)
#pragma unroll
                for (int nt = 0; nt < 8; nt++) MMA16816(acc[mt][nt], ah[mt], bh[nt]);
#pragma unroll
            for (int mt = 0; mt < 2; mt++)
#pragma unroll
                for (int nt = 0; nt < 8; nt++) MMA16816(acc[mt][nt], ah[mt], bl[nt]);
#pragma unroll
            for (int mt = 0; mt < 2; mt++)
#pragma unroll
                for (int nt = 0; nt < 8; nt++) MMA16816(acc[mt][nt], al[mt], bh[nt]);
        }
        __syncthreads();
        if (k + 2 < NKCH) LOAD_CHUNK(k + 2, k & 1);
    }
#undef LOAD_CHUNK

    int gid = lane >> 2, tig = lane & 3;
#pragma unroll
    for (int mt = 0; mt < 2; mt++) {
        int m0 = brow + wm + mt * 16 + gid;
#pragma unroll
        for (int nt = 0; nt < 8; nt++) {
            int n0 = bcol + wn + nt * 8 + tig * 2;
            float2 bb = *(const float2*)(bias + n0);
            float v0 = acc[mt][nt][0] + bb.x, v1 = acc[mt][nt][1] + bb.y;
            float v2 = acc[mt][nt][2] + bb.x, v3 = acc[mt][nt][3] + bb.y;
            if (Ch) {
                bf16 h0=__float2bfloat16(v0), h1=__float2bfloat16(v1);
                bf16 h2=__float2bfloat16(v2), h3=__float2bfloat16(v3);
                *(uint32_t*)(Ch + (size_t)m0 * HID + n0) =
                    (uint32_t)__bfloat16_as_ushort(h0) | ((uint32_t)__bfloat16_as_ushort(h1) << 16);
                *(uint32_t*)(Ch + (size_t)(m0+8) * HID + n0) =
                    (uint32_t)__bfloat16_as_ushort(h2) | ((uint32_t)__bfloat16_as_ushort(h3) << 16);
                *(uint32_t*)(Cl + (size_t)m0 * HID + n0) =
                    pack_bf2(v0 - __bfloat162float(h0), v1 - __bfloat162float(h1));
                *(uint32_t*)(Cl + (size_t)(m0+8) * HID + n0) =
                    pack_bf2(v2 - __bfloat162float(h2), v3 - __bfloat162float(h3));
            } else {
                *(float2*)(C + (size_t)m0 * HID + n0)     = make_float2(v0, v1);
                *(float2*)(C + (size_t)(m0+8) * HID + n0) = make_float2(v2, v3);
            }
        }
    }
}

// ================ attention scores: S = scale * Q @ K^T (HMMA) ===============
#define SNK (HD/BK)   // 4
__global__ void __launch_bounds__(256) attn_scores_mma()
{
    extern __shared__ __align__(128) char smg[];
    uint32_t sb = smem_u32(smg);
    int tid = threadIdx.x, lane = tid & 31, wid = tid >> 5;
    int kt = blockIdx.x, qt = blockIdx.y, bh = blockIdx.z;
    int b = bh >> 4, h = bh & 15;
    int wm = (wid >> 1) * 32, wn = (wid & 1) * 64;

    int lr = tid >> 2, lc = (tid & 3) * 8;
    const bf16* srcA0h = g_hQs + (size_t)(b*S + qt*128 + lr) * HID + h*HD + lc;
    const bf16* srcA1h = srcA0h + (size_t)64 * HID;
    const bf16* srcA0l = g_lQs + (size_t)(b*S + qt*128 + lr) * HID + h*HD + lc;
    const bf16* srcA1l = srcA0l + (size_t)64 * HID;
    const bf16* srcB0h = g_hKs + (size_t)(b*S + kt*128 + lr) * HID + h*HD + lc;
    const bf16* srcB1h = srcB0h + (size_t)64 * HID;
    const bf16* srcB0l = g_lKs + (size_t)(b*S + kt*128 + lr) * HID + h*HD + lc;
    const bf16* srcB1l = srcB0l + (size_t)64 * HID;
    uint32_t d0 = (uint32_t)(lr * SSTR + lc) * 2;
    uint32_t d1 = (uint32_t)((lr + 64) * SSTR + lc) * 2;

#define LOAD_CHUNK(kk, st) do { \
    uint32_t bb = sb + (uint32_t)(st) * STAGEB; \
    int k0 = (kk) * BK; \
    CP16(bb + 0*MATB + d0, srcA0h + k0); CP16(bb + 0*MATB + d1, srcA1h + k0); \
    CP16(bb + 1*MATB + d0, srcA0l + k0); CP16(bb + 1*MATB + d1, srcA1l + k0); \
    CP16(bb + 2*MATB + d0, srcB0h + k0); CP16(bb + 2*MATB + d1, srcB1h + k0); \
    CP16(bb + 3*MATB + d0, srcB0l + k0); CP16(bb + 3*MATB + d1, srcB1l + k0); \
    CP_COMMIT(); } while (0)

    uint32_t a_off = (uint32_t)((wm + (lane & 15)) * SSTR + ((lane >> 1) & 8)) * 2;
    uint32_t b_off = (uint32_t)((wn + (lane & 7)) * SSTR + (lane & 8)) * 2;

    float acc[2][8][4];
#pragma unroll
    for (int mt = 0; mt < 2; mt++)
#pragma unroll
        for (int nt = 0; nt < 8; nt++)
#pragma unroll
            for (int j = 0; j < 4; j++) acc[mt][nt][j] = 0.0f;

    LOAD_CHUNK(0, 0);
    LOAD_CHUNK(1, 1);

    for (int k = 0; k < SNK; k++) {
        if (k < SNK - 2) { CP_WAIT1(); } else { CP_WAIT0(); }
        __syncthreads();
        uint32_t stb = sb + (uint32_t)(k & 1) * STAGEB;
#pragma unroll
        for (int kst = 0; kst < 2; kst++) {
            uint32_t kb = (uint32_t)kst * 32;
            uint32_t ah[2][4], al[2][4];
            LDSM4(ah[0], stb + 0*MATB + a_off + kb);
            LDSM4(ah[1], stb + 0*MATB + a_off + kb + 16*SSTR*2);
            LDSM4(al[0], stb + 1*MATB + a_off + kb);
            LDSM4(al[1], stb + 1*MATB + a_off + kb + 16*SSTR*2);
            uint32_t bh_[8][2], bl_[8][2];
#pragma unroll
            for (int nt = 0; nt < 8; nt++) {
                LDSM2(bh_[nt], stb + 2*MATB + b_off + kb + nt*8*SSTR*2);
                LDSM2(bl_[nt], stb + 3*MATB + b_off + kb + nt*8*SSTR*2);
            }
#pragma unroll
            for (int mt = 0; mt < 2; mt++)
#pragma unroll
                for (int nt = 0; nt < 8; nt++) MMA16816(acc[mt][nt], ah[mt], bh_[nt]);
#pragma unroll
            for (int mt = 0; mt < 2; mt++)
#pragma unroll
                for (int nt = 0; nt < 8; nt++) MMA16816(acc[mt][nt], ah[mt], bl_[nt]);
#pragma unroll
            for (int mt = 0; mt < 2; mt++)
#pragma unroll
                for (int nt = 0; nt < 8; nt++) MMA16816(acc[mt][nt], al[mt], bh_[nt]);
        }
        __syncthreads();
        if (k + 2 < SNK) LOAD_CHUNK(k + 2, k & 1);
    }
#undef LOAD_CHUNK

    const float scale = 0.08838834764831843f;   // 1/sqrt(128)
#pragma unroll
    for (int mt = 0; mt < 2; mt++)
#pragma unroll
        for (int nt = 0; nt < 8; nt++)
#pragma unroll
            for (int j = 0; j < 4; j++) acc[mt][nt][j] *= scale;

    int gid = lane >> 2, tig = lane & 3;
    size_t srow0 = (size_t)bh * S + (size_t)qt * 128;
#pragma unroll
    for (int mt = 0; mt < 2; mt++) {
        size_t m0 = srow0 + wm + mt * 16 + gid;
#pragma unroll
        for (int nt = 0; nt < 8; nt++) {
            int n0 = kt * 128 + wn + nt * 8 + tig * 2;
            *(float2*)&g_Sc[m0 * S + n0]       = make_float2(acc[mt][nt][0], acc[mt][nt][1]);
            *(float2*)&g_Sc[(m0 + 8) * S + n0] = make_float2(acc[mt][nt][2], acc[mt][nt][3]);
        }
    }

    __syncthreads();
    float* sm = (float*)smg;          // [2][128]
    float* sl = sm + 256;             // [2][128]
#pragma unroll
    for (int mt = 0; mt < 2; mt++) {
#pragma unroll
        for (int half = 0; half < 2; half++) {
            float mx = -1e30f;
#pragma unroll
            for (int nt = 0; nt < 8; nt++)
                mx = fmaxf(mx, fmaxf(acc[mt][nt][half*2], acc[mt][nt][half*2+1]));
            mx = fmaxf(mx, __shfl_xor_sync(0xffffffffu, mx, 1));
            mx = fmaxf(mx, __shfl_xor_sync(0xffffffffu, mx, 2));
            float se = 0.0f;
#pragma unroll
            for (int nt = 0; nt < 8; nt++)
                se += __expf(acc[mt][nt][half*2] - mx) + __expf(acc[mt][nt][half*2+1] - mx);
            se += __shfl_xor_sync(0xffffffffu, se, 1);
            se += __shfl_xor_sync(0xffffffffu, se, 2);
            if (tig == 0) {
                int r = wm + mt * 16 + half * 8 + gid;
                sm[(wid & 1) * 128 + r] = mx;
                sl[(wid & 1) * 128 + r] = se;
            }
        }
    }
    __syncthreads();
    if (tid < 128) {
        float m0 = sm[tid], m1 = sm[128 + tid];
        float l0 = sl[tid], l1 = sl[128 + tid];
        float M = fmaxf(m0, m1);
        float L = l0 * __expf(m0 - M) + l1 * __expf(m1 - M);
        size_t q = (size_t)bh * S + (size_t)qt * 128 + tid;
        g_pm[q * 16 + kt] = M;
        g_pl[q * 16 + kt] = L;
    }
}

// ================ combine partial stats -> m, 1/l ============================
__global__ void __launch_bounds__(256) combine_stats()
{
    int r = blockIdx.x * 256 + threadIdx.x;     // 0..65535
    float M = -1e30f;
#pragma unroll
    for (int i = 0; i < 16; i++) M = fmaxf(M, g_pm[(size_t)r * 16 + i]);
    float L = 0.0f;
#pragma unroll
    for (int i = 0; i < 16; i++)
        L += g_pl[(size_t)r * 16 + i] * __expf(g_pm[(size_t)r * 16 + i] - M);
    g_m[r]  = M;
    g_li[r] = 1.0f / L;
}

// ================ attn AV: attended = softmax(S) @ V (HMMA) ==================
// A = P on the fly from raw scores (p written back to g_Sc for mean kernel);
// B = V^T pre-split. Epilogue writes attended hi/lo into g_hA/g_lA.
__global__ void __launch_bounds__(256) attn_av_mma()
{
    extern __shared__ __align__(128) char smg[];
    uint32_t sb = smem_u32(smg);
    float* msh = (float*)(smg + GSMEM);        // [128]
    float* lih = msh + 128;                    // [128]
    int tid = threadIdx.x, lane = tid & 31, wid = tid >> 5;
    int qt = blockIdx.x, b = blockIdx.y, h = blockIdx.z;
    int bh = b * NH + h;
    int wm = (wid >> 1) * 32, wn = (wid & 1) * 64;

    if (tid < 128) {
        size_t q = (size_t)bh * S + (size_t)qt * 128 + tid;
        msh[tid] = g_m[q];
        lih[tid] = g_li[q];
    }
    __syncthreads();

    int pr = tid >> 1, pc = (tid & 1) * 16;
    float* srcP = g_Sc + ((size_t)bh * S + (size_t)qt * 128 + pr) * S + pc;
    float pm_r = msh[pr], pli_r = lih[pr];
    uint32_t pdst = (uint32_t)(pr * SSTR + pc) * 2;

    int lr = tid >> 2, lc = (tid & 3) * 8;
    const bf16* srcV0h = g_hVt + (size_t)(h*HD + lr) * MROWS + b*S + lc;
    const bf16* srcV1h = srcV0h + (size_t)64 * MROWS;
    const bf16* srcV0l = g_lVt + (size_t)(h*HD + lr) * MROWS + b*S + lc;
    const bf16* srcV1l = srcV0l + (size_t)64 * MROWS;
    uint32_t d0 = (uint32_t)(lr * SSTR + lc) * 2;
    uint32_t d1 = (uint32_t)((lr + 64) * SSTR + lc) * 2;

#define LOADV(kk, st) do { \
    uint32_t bb = sb + (uint32_t)(st) * STAGEB; \
    int k0 = (kk) * BK; \
    CP16(bb + 2*MATB + d0, srcV0h + k0); CP16(bb + 2*MATB + d1, srcV1h + k0); \
    CP16(bb + 3*MATB + d0, srcV0l + k0); CP16(bb + 3*MATB + d1, srcV1l + k0); \
    CP_COMMIT(); } while (0)

// convert scores to p, stash bf16 hi/lo in smem, AND write p back to g_Sc
#define CONVP(kk, st) do { \
    uint32_t bb = sb + (uint32_t)(st) * STAGEB; \
    int k0 = (kk) * BK; \
    _Pragma("unroll") \
    for (int j = 0; j < 4; j++) { \
        float4 v = *(const float4*)(srcP + k0 + j * 4); \
        float p0 = __expf(v.x - pm_r) * pli_r; \
        float p1 = __expf(v.y - pm_r) * pli_r; \
        float p2 = __expf(v.z - pm_r) * pli_r; \
        float p3 = __expf(v.w - pm_r) * pli_r; \
        *(float4*)(srcP + k0 + j * 4) = make_float4(p0, p1, p2, p3); \
        bf16 h0=__float2bfloat16(p0), h1=__float2bfloat16(p1); \
        bf16 h2=__float2bfloat16(p2), h3=__float2bfloat16(p3); \
        uint32_t hi0 = (uint32_t)__bfloat16_as_ushort(h0) | ((uint32_t)__bfloat16_as_ushort(h1) << 16); \
        uint32_t hi1 = (uint32_t)__bfloat16_as_ushort(h2) | ((uint32_t)__bfloat16_as_ushort(h3) << 16); \
        uint32_t lo0 = pack_bf2(p0 - __bfloat162float(h0), p1 - __bfloat162float(h1)); \
        uint32_t lo1 = pack_bf2(p2 - __bfloat162float(h2), p3 - __bfloat162float(h3)); \
        uint32_t ad = pdst + (uint32_t)j * 8; \
        asm volatile("st.shared.v2.b32 [%0], {%1, %2};" :: "r"(bb + 0*MATB + ad), "r"(hi0), "r"(hi1)); \
        asm volatile("st.shared.v2.b32 [%0], {%1, %2};" :: "r"(bb + 1*MATB + ad), "r"(lo0), "r"(lo1)); \
    } } while (0)

    uint32_t a_off = (uint32_t)((wm + (lane & 15)) * SSTR + ((lane >> 1) & 8)) * 2;
    uint32_t b_off = (uint32_t)((wn + (lane & 7)) * SSTR + (lane & 8)) * 2;

    float acc[2][8][4];
#pragma unroll
    for (int mt = 0; mt < 2; mt++)
#pragma unroll
        for (int nt = 0; nt < 8; nt++)
#pragma unroll
            for (int j = 0; j < 4; j++) acc[mt][nt][j] = 0.0f;

    LOADV(0, 0);
    LOADV(1, 1);

    for (int k = 0; k < NKCH; k++) {        // 64 chunks of 32 seq positions
        if (k < NKCH - 2) { CP_WAIT1(); } else { CP_WAIT0(); }
        CONVP(k, k & 1);
        __syncthreads();
        uint32_t stb = sb + (uint32_t)(k & 1) * STAGEB;
#pragma unroll
        for (int kst = 0; kst < 2; kst++) {
            uint32_t kb = (uint32_t)kst * 32;
            uint32_t ah[2][4], al[2][4];
            LDSM4(ah[0], stb + 0*MATB + a_off + kb);
            LDSM4(ah[1], stb + 0*MATB + a_off + kb + 16*SSTR*2);
            LDSM4(al[0], stb + 1*MATB + a_off + kb);
            LDSM4(al[1], stb + 1*MATB + a_off + kb + 16*SSTR*2);
            uint32_t bh_[8][2], bl_[8][2];
#pragma unroll
            for (int nt = 0; nt < 8; nt++) {
                LDSM2(bh_[nt], stb + 2*MATB + b_off + kb + nt*8*SSTR*2);
                LDSM2(bl_[nt], stb + 3*MATB + b_off + kb + nt*8*SSTR*2);
            }
#pragma unroll
            for (int mt = 0; mt < 2; mt++)
#pragma unroll
                for (int nt = 0; nt < 8; nt++) MMA16816(acc[mt][nt], ah[mt], bh_[nt]);
#pragma unroll
            for (int mt = 0; mt < 2; mt++)
#pragma unroll
                for (int nt = 0; nt < 8; nt++) MMA16816(acc[mt][nt], ah[mt], bl_[nt]);
#pragma unroll
            for (int mt = 0; mt < 2; mt++)
#pragma unroll
                for (int nt = 0; nt < 8; nt++) MMA16816(acc[mt][nt], al[mt], bh_[nt]);
        }
        __syncthreads();
        if (k + 2 < NKCH) LOADV(k + 2, k & 1);
    }
#undef LOADV
#undef CONVP

    int gid = lane >> 2, tig = lane & 3;
#pragma unroll
    for (int mt = 0; mt < 2; mt++) {
        size_t m0 = (size_t)(b * S + qt * 128 + wm + mt * 16 + gid);
#pragma unroll
        for (int nt = 0; nt < 8; nt++) {
            int n0 = h * HD + wn + nt * 8 + tig * 2;
            float v0 = acc[mt][nt][0], v1 = acc[mt][nt][1];
            float v2 = acc[mt][nt][2], v3 = acc[mt][nt][3];
            bf16 h0=__float2bfloat16(v0), h1=__float2bfloat16(v1);
            bf16 h2=__float2bfloat16(v2), h3=__float2bfloat16(v3);
            *(uint32_t*)(g_hA + m0 * HID + n0) =
                (uint32_t)__bfloat16_as_ushort(h0) | ((uint32_t)__bfloat16_as_ushort(h1) << 16);
            *(uint32_t*)(g_hA + (m0+8) * HID + n0) =
                (uint32_t)__bfloat16_as_ushort(h2) | ((uint32_t)__bfloat16_as_ushort(h3) << 16);
            *(uint32_t*)(g_lA + m0 * HID + n0) =
                pack_bf2(v0 - __bfloat162float(h0), v1 - __bfloat162float(h1));
            *(uint32_t*)(g_lA + (m0+8) * HID + n0) =
                pack_bf2(v2 - __bfloat162float(h2), v3 - __bfloat162float(h3));
        }
    }
}

// ---------------- head-mean of attention weights (pure bandwidth) -----------
__global__ void __launch_bounds__(256) mean_attn(float* __restrict__ out2)
{
    int f = blockIdx.x * 256 + threadIdx.x;      // float4 index, 2,097,152 total
    int b  = f >> 20;
    int r  = f & 1048575;
    int q  = r >> 9;
    int k4 = (r & 511) * 4;
    float4 acc = make_float4(0.f, 0.f, 0.f, 0.f);
    size_t base = ((size_t)(b * NH)) * S * S + (size_t)q * S + k4;
#pragma unroll
    for (int h2 = 0; h2 < NH; h2++) {
        float4 v = *(const float4*)&g_Sc[base + (size_t)h2 * S * S];
        acc.x += v.x; acc.y += v.y; acc.z += v.z; acc.w += v.w;
    }
    const float inv = 1.0f / 16.0f;
    acc.x *= inv; acc.y *= inv; acc.z *= inv; acc.w *= inv;
    *(float4*)&out2[(size_t)f * 4] = acc;
}

// ---------------- launch ----------------------------------------------------
extern "C" void kernel_launch(void* const* d_in, const int* in_sizes, int n_in,
                              void* d_out, int out_size)
{
    const float* query = (const float*)d_in[0];
    const float* key   = (const float*)d_in[1];
    const float* value = (const float*)d_in[2];
    // d_in[3] rewards, d_in[4] mask: mathematically no-ops
    const float* Wq = (const float*)d_in[5];
    const float* bq = (const float*)d_in[6];
    const float* Wk = (const float*)d_in[7];
    const float* bk = (const float*)d_in[8];
    const float* Wv = (const float*)d_in[9];
    const float* bv = (const float*)d_in[10];
    const float* Wo = (const float*)d_in[11];
    const float* bo = (const float*)d_in[12];
    float* out = (float*)d_out;

    float *pV;
    cudaGetSymbolAddress((void**)&pV, g_V);
    bf16 *hA, *lA, *hW, *lW, *hQs, *lQs, *hKs, *lKs, *hVt, *lVt;
    cudaGetSymbolAddress((void**)&hA, g_hA);
    cudaGetSymbolAddress((void**)&lA, g_lA);
    cudaGetSymbolAddress((void**)&hW, g_hW);
    cudaGetSymbolAddress((void**)&lW, g_lW);
    cudaGetSymbolAddress((void**)&hQs, g_hQs);
    cudaGetSymbolAddress((void**)&lQs, g_lQs);
    cudaGetSymbolAddress((void**)&hKs, g_hKs);
    cudaGetSymbolAddress((void**)&lKs, g_lKs);
    cudaGetSymbolAddress((void**)&hVt, g_hVt);
    cudaGetSymbolAddress((void**)&lVt, g_lVt);

    cudaFuncSetAttribute(gemm_hmma,       cudaFuncAttributeMaxDynamicSharedMemorySize, GSMEM);
    cudaFuncSetAttribute(attn_scores_mma, cudaFuncAttributeMaxDynamicSharedMemorySize, GSMEM);
    cudaFuncSetAttribute(attn_av_mma,     cudaFuncAttributeMaxDynamicSharedMemorySize, AVSMEM);

    const int NA4 = MROWS * HID / 4;
    dim3 tw(HID / 32, HID / 32), tb(32, 8);
    dim3 gg(HID / 128, MROWS / 128);   // (16, 32)

    // Q projection -> split bf16
    split_hi_lo<<<NA4 / 256, 256>>>(query, hA, lA, NA4);
    transpose_split<<<tw, tb>>>(Wq, hW, lW, HID, HID);
    gemm_hmma<<<gg, 256, GSMEM>>>(hA, lA, hW, lW, bq, nullptr, hQs, lQs);
    // K projection -> split bf16
    split_hi_lo<<<NA4 / 256, 256>>>(key, hA, lA, NA4);
    transpose_split<<<tw, tb>>>(Wk, hW, lW, HID, HID);
    gemm_hmma<<<gg, 256, GSMEM>>>(hA, lA, hW, lW, bk, nullptr, hKs, lKs);
    // V projection -> fp32, then transpose+split
    split_hi_lo<<<NA4 / 256, 256>>>(value, hA, lA, NA4);
    transpose_split<<<tw, tb>>>(Wv, hW, lW, HID, HID);
    gemm_hmma<<<gg, 256, GSMEM>>>(hA, lA, hW, lW, bv, pV, nullptr, nullptr);
    transpose_split<<<dim3(HID / 32, MROWS / 32), tb>>>(pV, hVt, lVt, HID, MROWS);

    // attention
    attn_scores_mma<<<dim3(S / 128, S / 128, BATCH * NH), 256, GSMEM>>>();
    combine_stats<<<(BATCH * NH * S) / 256, 256>>>();
    attn_av_mma<<<dim3(S / 128, BATCH, NH), 256, AVSMEM>>>();

    if (out_size >= 2 * MROWS * HID) {
        mean_attn<<<(BATCH * S * S / 4) / 256, 256>>>(out + (size_t)MROWS * HID);
    }

    // O projection (A already split by attn_av epilogue)
    transpose_split<<<tw, tb>>>(Wo, hW, lW, HID, HID);
    gemm_hmma<<<gg, 256, GSMEM>>>(hA, lA, hW, lW, bo, out, nullptr, nullptr);
}

// round 13
// speedup vs baseline: 2.2953x; 2.2953x over previous
#include <cuda_runtime.h>
#include <cuda_fp16.h>
#include <cstdint>

#define S 2048
#define HID 2048
#define NH 16
#define HD 128
#define BATCH 2
#define MROWS (BATCH*S)   // 4096

typedef unsigned long long ull;

// ---------------- scratch (static device allocations; no cudaMalloc) --------
__device__ float g_V [(size_t)MROWS*HID];
__device__ float g_Sc[(size_t)BATCH*NH*S*S];   // raw scaled scores (536 MB)
__device__ float g_m [BATCH*NH*S];
__device__ float g_li[BATCH*NH*S];
__device__ float g_pm[(size_t)BATCH*NH*S*16];  // per-(row, ktile) partial max
__device__ float g_pl[(size_t)BATCH*NH*S*16];  // per-(row, ktile) partial sumexp

__device__ __half g_fA [(size_t)MROWS*HID];    // GEMM A operand / attended
__device__ __half g_fW [(size_t)HID*HID];      // weight, transposed [N,K]
__device__ __half g_fQ [(size_t)MROWS*HID];    // Q projection (fp16)
__device__ __half g_fK [(size_t)MROWS*HID];    // K projection (fp16)
__device__ __half g_fVt[(size_t)HID*MROWS];    // V^T (fp16) [HID x MROWS]

// ======================= PTX helpers =========================================
__device__ __forceinline__ uint32_t smem_u32(const void* p){
    uint32_t a;
    asm("{ .reg .u64 t; cvta.to.shared.u64 t, %1; cvt.u32.u64 %0, t; }" : "=r"(a) : "l"(p));
    return a;
}
#define CP16(sm, gp)  asm volatile("cp.async.cg.shared.global [%0], [%1], 16;" :: "r"(sm), "l"(gp) : "memory")
#define CP_COMMIT()   asm volatile("cp.async.commit_group;" ::: "memory")
#define CP_WAIT1()    asm volatile("cp.async.wait_group 1;" ::: "memory")
#define CP_WAIT0()    asm volatile("cp.async.wait_group 0;" ::: "memory")

#define LDSM4(R, A) asm volatile("ldmatrix.sync.aligned.m8n8.x4.shared.b16 {%0,%1,%2,%3}, [%4];" \
    : "=r"((R)[0]), "=r"((R)[1]), "=r"((R)[2]), "=r"((R)[3]) : "r"(A))

#define MMAF16(D, Af, B0, B1) asm volatile( \
    "mma.sync.aligned.m16n8k16.row.col.f32.f16.f16.f32 " \
    "{%0,%1,%2,%3}, {%4,%5,%6,%7}, {%8,%9}, {%0,%1,%2,%3};" \
    : "+f"((D)[0]), "+f"((D)[1]), "+f"((D)[2]), "+f"((D)[3]) \
    : "r"((Af)[0]), "r"((Af)[1]), "r"((Af)[2]), "r"((Af)[3]), \
      "r"(B0), "r"(B1))

__device__ __forceinline__ uint32_t h2u(float a, float b){
    __half2 h = __floats2half2_rn(a, b);
    return *(uint32_t*)&h;
}

// ======================= prep kernels ========================================
__global__ void __launch_bounds__(256) cvt_f16(
    const float* __restrict__ in, __half* __restrict__ out, int n4)
{
    int i = blockIdx.x * 256 + threadIdx.x;
    if (i >= n4) return;
    float4 v = ((const float4*)in)[i];
    uint32_t a = h2u(v.x, v.y), b = h2u(v.z, v.w);
    ((uint2*)out)[i] = make_uint2(a, b);
}

// in [RI x CI] fp32 -> out [CI x RI] fp16 (transpose)
__global__ void __launch_bounds__(256) transpose_f16(
    const float* __restrict__ in, __half* __restrict__ out, int CI, int RI)
{
    __shared__ float ts[32][33];
    int tx = threadIdx.x, ty = threadIdx.y;          // block (32,8)
    int n0 = blockIdx.x * 32, k0 = blockIdx.y * 32;
#pragma unroll
    for (int j = 0; j < 4; j++)
        ts[ty + j * 8][tx] = in[(size_t)(k0 + ty + j * 8) * CI + n0 + tx];
    __syncthreads();
#pragma unroll
    for (int j = 0; j < 4; j++)
        out[(size_t)(n0 + ty + j * 8) * RI + k0 + tx] = __float2half(ts[tx][ty + j * 8]);
}

// ======================= fp16 HMMA GEMM: C = A@W + bias ======================
// A [M,K] fp16 row-major; B [N,K] fp16 (transposed weight). Tile 128x128, BK=32.
#define BK 32
#define NKCH (HID/BK)                 // 64
#define SSTR 40                       // fp16 per smem row (pad 32->40)
#define MATB (128*SSTR*2)             // 10240 B per matrix tile
#define STG2 (2*MATB)                 // A + B: 20480 B
#define GSM2 (2*STG2)                 // 40960 B
#define AVS  (GSM2 + 1024)

__global__ void __launch_bounds__(256) gemm_f16(
    const __half* __restrict__ A, const __half* __restrict__ B,
    const float* __restrict__ bias, float* __restrict__ C,
    __half* __restrict__ Cf)
{
    extern __shared__ __align__(128) char smg[];
    uint32_t sb = smem_u32(smg);
    int tid = threadIdx.x, lane = tid & 31, wid = tid >> 5;
    int brow = blockIdx.y * 128, bcol = blockIdx.x * 128;
    int wm = (wid >> 1) * 32, wn = (wid & 1) * 64;

    int lr = tid >> 2, lc = (tid & 3) * 8;
    const __half* srcA0 = A + (size_t)(brow + lr) * HID + lc;
    const __half* srcA1 = A + (size_t)(brow + lr + 64) * HID + lc;
    const __half* srcB0 = B + (size_t)(bcol + lr) * HID + lc;
    const __half* srcB1 = B + (size_t)(bcol + lr + 64) * HID + lc;
    uint32_t d0 = (uint32_t)(lr * SSTR + lc) * 2;
    uint32_t d1 = (uint32_t)((lr + 64) * SSTR + lc) * 2;

#define LOAD_CHUNK(kk, st) do { \
    uint32_t bb = sb + (uint32_t)(st) * STG2; \
    int k0 = (kk) * BK; \
    CP16(bb + d0, srcA0 + k0); CP16(bb + d1, srcA1 + k0); \
    CP16(bb + MATB + d0, srcB0 + k0); CP16(bb + MATB + d1, srcB1 + k0); \
    CP_COMMIT(); } while (0)

    uint32_t a_off = (uint32_t)((wm + (lane & 15)) * SSTR + ((lane >> 1) & 8)) * 2;
    // B x4: two adjacent 8-row n-tiles per ldmatrix
    uint32_t b4_off = (uint32_t)((wn + (lane & 7) + ((lane >> 4) << 3)) * SSTR + (lane & 8)) * 2;

    float acc[2][8][4];
#pragma unroll
    for (int mt = 0; mt < 2; mt++)
#pragma unroll
        for (int nt = 0; nt < 8; nt++)
#pragma unroll
            for (int j = 0; j < 4; j++) acc[mt][nt][j] = 0.0f;

    LOAD_CHUNK(0, 0);
    LOAD_CHUNK(1, 1);

    for (int k = 0; k < NKCH; k++) {
        if (k < NKCH - 2) { CP_WAIT1(); } else { CP_WAIT0(); }
        __syncthreads();
        uint32_t stb = sb + (uint32_t)(k & 1) * STG2;
#pragma unroll
        for (int kst = 0; kst < 2; kst++) {
            uint32_t kb = (uint32_t)kst * 32;
            uint32_t a[2][4], b4[4][4];
            LDSM4(a[0], stb + a_off + kb);
            LDSM4(a[1], stb + a_off + kb + 16*SSTR*2);
#pragma unroll
            for (int g = 0; g < 4; g++)
                LDSM4(b4[g], stb + MATB + b4_off + kb + g*16*SSTR*2);
#pragma unroll
            for (int mt = 0; mt < 2; mt++)
#pragma unroll
                for (int g = 0; g < 4; g++) {
                    MMAF16(acc[mt][2*g],   a[mt], b4[g][0], b4[g][1]);
                    MMAF16(acc[mt][2*g+1], a[mt], b4[g][2], b4[g][3]);
                }
        }
        __syncthreads();
        if (k + 2 < NKCH) LOAD_CHUNK(k + 2, k & 1);
    }
#undef LOAD_CHUNK

    int gid = lane >> 2, tig = lane & 3;
#pragma unroll
    for (int mt = 0; mt < 2; mt++) {
        int m0 = brow + wm + mt * 16 + gid;
#pragma unroll
        for (int nt = 0; nt < 8; nt++) {
            int n0 = bcol + wn + nt * 8 + tig * 2;
            float2 bb = *(const float2*)(bias + n0);
            float v0 = acc[mt][nt][0] + bb.x, v1 = acc[mt][nt][1] + bb.y;
            float v2 = acc[mt][nt][2] + bb.x, v3 = acc[mt][nt][3] + bb.y;
            if (Cf) {
                *(uint32_t*)(Cf + (size_t)m0 * HID + n0)     = h2u(v0, v1);
                *(uint32_t*)(Cf + (size_t)(m0+8) * HID + n0) = h2u(v2, v3);
            } else {
                *(float2*)(C + (size_t)m0 * HID + n0)     = make_float2(v0, v1);
                *(float2*)(C + (size_t)(m0+8) * HID + n0) = make_float2(v2, v3);
            }
        }
    }
}

// ================ attention scores: S = scale * Q @ K^T (fp16 HMMA) =========
#define SNK (HD/BK)   // 4
__global__ void __launch_bounds__(256) attn_scores_mma()
{
    extern __shared__ __align__(128) char smg[];
    uint32_t sb = smem_u32(smg);
    int tid = threadIdx.x, lane = tid & 31, wid = tid >> 5;
    int kt = blockIdx.x, qt = blockIdx.y, bh = blockIdx.z;
    int b = bh >> 4, h = bh & 15;
    int wm = (wid >> 1) * 32, wn = (wid & 1) * 64;

    int lr = tid >> 2, lc = (tid & 3) * 8;
    const __half* srcA0 = g_fQ + (size_t)(b*S + qt*128 + lr) * HID + h*HD + lc;
    const __half* srcA1 = srcA0 + (size_t)64 * HID;
    const __half* srcB0 = g_fK + (size_t)(b*S + kt*128 + lr) * HID + h*HD + lc;
    const __half* srcB1 = srcB0 + (size_t)64 * HID;
    uint32_t d0 = (uint32_t)(lr * SSTR + lc) * 2;
    uint32_t d1 = (uint32_t)((lr + 64) * SSTR + lc) * 2;

#define LOAD_CHUNK(kk, st) do { \
    uint32_t bb = sb + (uint32_t)(st) * STG2; \
    int k0 = (kk) * BK; \
    CP16(bb + d0, srcA0 + k0); CP16(bb + d1, srcA1 + k0); \
    CP16(bb + MATB + d0, srcB0 + k0); CP16(bb + MATB + d1, srcB1 + k0); \
    CP_COMMIT(); } while (0)

    uint32_t a_off  = (uint32_t)((wm + (lane & 15)) * SSTR + ((lane >> 1) & 8)) * 2;
    uint32_t b4_off = (uint32_t)((wn + (lane & 7) + ((lane >> 4) << 3)) * SSTR + (lane & 8)) * 2;

    float acc[2][8][4];
#pragma unroll
    for (int mt = 0; mt < 2; mt++)
#pragma unroll
        for (int nt = 0; nt < 8; nt++)
#pragma unroll
            for (int j = 0; j < 4; j++) acc[mt][nt][j] = 0.0f;

    LOAD_CHUNK(0, 0);
    LOAD_CHUNK(1, 1);

    for (int k = 0; k < SNK; k++) {
        if (k < SNK - 2) { CP_WAIT1(); } else { CP_WAIT0(); }
        __syncthreads();
        uint32_t stb = sb + (uint32_t)(k & 1) * STG2;
#pragma unroll
        for (int kst = 0; kst < 2; kst++) {
            uint32_t kb = (uint32_t)kst * 32;
            uint32_t a[2][4], b4[4][4];
            LDSM4(a[0], stb + a_off + kb);
            LDSM4(a[1], stb + a_off + kb + 16*SSTR*2);
#pragma unroll
            for (int g = 0; g < 4; g++)
                LDSM4(b4[g], stb + MATB + b4_off + kb + g*16*SSTR*2);
#pragma unroll
            for (int mt = 0; mt < 2; mt++)
#pragma unroll
                for (int g = 0; g < 4; g++) {
                    MMAF16(acc[mt][2*g],   a[mt], b4[g][0], b4[g][1]);
                    MMAF16(acc[mt][2*g+1], a[mt], b4[g][2], b4[g][3]);
                }
        }
        __syncthreads();
        if (k + 2 < SNK) LOAD_CHUNK(k + 2, k & 1);
    }
#undef LOAD_CHUNK

    const float scale = 0.08838834764831843f;   // 1/sqrt(128)
#pragma unroll
    for (int mt = 0; mt < 2; mt++)
#pragma unroll
        for (int nt = 0; nt < 8; nt++)
#pragma unroll
            for (int j = 0; j < 4; j++) acc[mt][nt][j] *= scale;

    int gid = lane >> 2, tig = lane & 3;
    size_t srow0 = (size_t)bh * S + (size_t)qt * 128;
#pragma unroll
    for (int mt = 0; mt < 2; mt++) {
        size_t m0 = srow0 + wm + mt * 16 + gid;
#pragma unroll
        for (int nt = 0; nt < 8; nt++) {
            int n0 = kt * 128 + wn + nt * 8 + tig * 2;
            *(float2*)&g_Sc[m0 * S + n0]       = make_float2(acc[mt][nt][0], acc[mt][nt][1]);
            *(float2*)&g_Sc[(m0 + 8) * S + n0] = make_float2(acc[mt][nt][2], acc[mt][nt][3]);
        }
    }

    __syncthreads();
    float* sm = (float*)smg;          // [2][128]
    float* sl = sm + 256;             // [2][128]
#pragma unroll
    for (int mt = 0; mt < 2; mt++) {
#pragma unroll
        for (int half = 0; half < 2; half++) {
            float mx = -1e30f;
#pragma unroll
            for (int nt = 0; nt < 8; nt++)
                mx = fmaxf(mx, fmaxf(acc[mt][nt][half*2], acc[mt][nt][half*2+1]));
            mx = fmaxf(mx, __shfl_xor_sync(0xffffffffu, mx, 1));
            mx = fmaxf(mx, __shfl_xor_sync(0xffffffffu, mx, 2));
            float se = 0.0f;
#pragma unroll
            for (int nt = 0; nt < 8; nt++)
                se += __expf(acc[mt][nt][half*2] - mx) + __expf(acc[mt][nt][half*2+1] - mx);
            se += __shfl_xor_sync(0xffffffffu, se, 1);
            se += __shfl_xor_sync(0xffffffffu, se, 2);
            if (tig == 0) {
                int r = wm + mt * 16 + half * 8 + gid;
                sm[(wid & 1) * 128 + r] = mx;
                sl[(wid & 1) * 128 + r] = se;
            }
        }
    }
    __syncthreads();
    if (tid < 128) {
        float m0 = sm[tid], m1 = sm[128 + tid];
        float l0 = sl[tid], l1 = sl[128 + tid];
        float M = fmaxf(m0, m1);
        float L = l0 * __expf(m0 - M) + l1 * __expf(m1 - M);
        size_t q = (size_t)bh * S + (size_t)qt * 128 + tid;
        g_pm[q * 16 + kt] = M;
        g_pl[q * 16 + kt] = L;
    }
}

// ================ combine partial stats -> m, 1/l ============================
__global__ void __launch_bounds__(256) combine_stats()
{
    int r = blockIdx.x * 256 + threadIdx.x;     // 0..65535
    float M = -1e30f;
#pragma unroll
    for (int i = 0; i < 16; i++) M = fmaxf(M, g_pm[(size_t)r * 16 + i]);
    float L = 0.0f;
#pragma unroll
    for (int i = 0; i < 16; i++)
        L += g_pl[(size_t)r * 16 + i] * __expf(g_pm[(size_t)r * 16 + i] - M);
    g_m[r]  = M;
    g_li[r] = 1.0f / L;
}

// ================ attn AV: attended = softmax(S) @ V (fp16 HMMA) =============
// A = P on the fly from raw scores (fp16 into smem); B = V^T fp16 pre-built.
// Epilogue writes attended fp16 into g_fA for the O projection.
__global__ void __launch_bounds__(256) attn_av_mma()
{
    extern __shared__ __align__(128) char smg[];
    uint32_t sb = smem_u32(smg);
    float* msh = (float*)(smg + GSM2);         // [128]
    float* lih = msh + 128;                    // [128]
    int tid = threadIdx.x, lane = tid & 31, wid = tid >> 5;
    int qt = blockIdx.x, b = blockIdx.y, h = blockIdx.z;
    int bh = b * NH + h;
    int wm = (wid >> 1) * 32, wn = (wid & 1) * 64;

    if (tid < 128) {
        size_t q = (size_t)bh * S + (size_t)qt * 128 + tid;
        msh[tid] = g_m[q];
        lih[tid] = g_li[q];
    }
    __syncthreads();

    int pr = tid >> 1, pc = (tid & 1) * 16;
    const float* srcP = g_Sc + ((size_t)bh * S + (size_t)qt * 128 + pr) * S + pc;
    float pm_r = msh[pr], pli_r = lih[pr];
    uint32_t pdst = (uint32_t)(pr * SSTR + pc) * 2;

    int lr = tid >> 2, lc = (tid & 3) * 8;
    const __half* srcV0 = g_fVt + (size_t)(h*HD + lr) * MROWS + b*S + lc;
    const __half* srcV1 = srcV0 + (size_t)64 * MROWS;
    uint32_t d0 = (uint32_t)(lr * SSTR + lc) * 2;
    uint32_t d1 = (uint32_t)((lr + 64) * SSTR + lc) * 2;

#define LOADV(kk, st) do { \
    uint32_t bb = sb + (uint32_t)(st) * STG2; \
    int k0 = (kk) * BK; \
    CP16(bb + MATB + d0, srcV0 + k0); CP16(bb + MATB + d1, srcV1 + k0); \
    CP_COMMIT(); } while (0)

// convert scores to p (fp16) into smem P tile
#define CONVP(kk, st) do { \
    uint32_t bb = sb + (uint32_t)(st) * STG2; \
    int k0 = (kk) * BK; \
    _Pragma("unroll") \
    for (int j = 0; j < 4; j++) { \
        float4 v = *(const float4*)(srcP + k0 + j * 4); \
        float p0 = __expf(v.x - pm_r) * pli_r; \
        float p1 = __expf(v.y - pm_r) * pli_r; \
        float p2 = __expf(v.z - pm_r) * pli_r; \
        float p3 = __expf(v.w - pm_r) * pli_r; \
        uint32_t u0 = h2u(p0, p1), u1 = h2u(p2, p3); \
        asm volatile("st.shared.v2.b32 [%0], {%1, %2};" :: "r"(bb + pdst + (uint32_t)j * 8), "r"(u0), "r"(u1)); \
    } } while (0)

    uint32_t a_off  = (uint32_t)((wm + (lane & 15)) * SSTR + ((lane >> 1) & 8)) * 2;
    uint32_t b4_off = (uint32_t)((wn + (lane & 7) + ((lane >> 4) << 3)) * SSTR + (lane & 8)) * 2;

    float acc[2][8][4];
#pragma unroll
    for (int mt = 0; mt < 2; mt++)
#pragma unroll
        for (int nt = 0; nt < 8; nt++)
#pragma unroll
            for (int j = 0; j < 4; j++) acc[mt][nt][j] = 0.0f;

    LOADV(0, 0);
    LOADV(1, 1);

    for (int k = 0; k < NKCH; k++) {        // 64 chunks of 32 seq positions
        if (k < NKCH - 2) { CP_WAIT1(); } else { CP_WAIT0(); }
        CONVP(k, k & 1);
        __syncthreads();
        uint32_t stb = sb + (uint32_t)(k & 1) * STG2;
#pragma unroll
        for (int kst = 0; kst < 2; kst++) {
            uint32_t kb = (uint32_t)kst * 32;
            uint32_t a[2][4], b4[4][4];
            LDSM4(a[0], stb + a_off + kb);
            LDSM4(a[1], stb + a_off + kb + 16*SSTR*2);
#pragma unroll
            for (int g = 0; g < 4; g++)
                LDSM4(b4[g], stb + MATB + b4_off + kb + g*16*SSTR*2);
#pragma unroll
            for (int mt = 0; mt < 2; mt++)
#pragma unroll
                for (int g = 0; g < 4; g++) {
                    MMAF16(acc[mt][2*g],   a[mt], b4[g][0], b4[g][1]);
                    MMAF16(acc[mt][2*g+1], a[mt], b4[g][2], b4[g][3]);
                }
        }
        __syncthreads();
        if (k + 2 < NKCH) LOADV(k + 2, k & 1);
    }
#undef LOADV
#undef CONVP

    int gid = lane >> 2, tig = lane & 3;
#pragma unroll
    for (int mt = 0; mt < 2; mt++) {
        size_t m0 = (size_t)(b * S + qt * 128 + wm + mt * 16 + gid);
#pragma unroll
        for (int nt = 0; nt < 8; nt++) {
            int n0 = h * HD + wn + nt * 8 + tig * 2;
            *(uint32_t*)(g_fA + m0 * HID + n0) =
                h2u(acc[mt][nt][0], acc[mt][nt][1]);
            *(uint32_t*)(g_fA + (m0+8) * HID + n0) =
                h2u(acc[mt][nt][2], acc[mt][nt][3]);
        }
    }
}

// ---------------- head-mean of attention weights (recompute p) --------------
__global__ void __launch_bounds__(256) mean_attn(float* __restrict__ out2)
{
    int f = blockIdx.x * 256 + threadIdx.x;
    int b  = f >> 20;
    int r  = f & 1048575;
    int q  = r >> 9;
    int k4 = (r & 511) * 4;
    float mm[NH], ll[NH];
#pragma unroll
    for (int h = 0; h < NH; h++) {
        int bh = b * NH + h;
        mm[h] = g_m[bh * S + q];
        ll[h] = g_li[bh * S + q];
    }
    float4 acc = make_float4(0.f, 0.f, 0.f, 0.f);
#pragma unroll
    for (int h = 0; h < NH; h++) {
        size_t base = ((size_t)(b * NH + h) * S + q) * S + k4;
        float4 v = *(const float4*)&g_Sc[base];
        acc.x += __expf(v.x - mm[h]) * ll[h];
        acc.y += __expf(v.y - mm[h]) * ll[h];
        acc.z += __expf(v.z - mm[h]) * ll[h];
        acc.w += __expf(v.w - mm[h]) * ll[h];
    }
    const float inv = 1.0f / 16.0f;
    acc.x *= inv; acc.y *= inv; acc.z *= inv; acc.w *= inv;
    *(float4*)&out2[(size_t)f * 4] = acc;
}

// ---------------- launch ----------------------------------------------------
extern "C" void kernel_launch(void* const* d_in, const int* in_sizes, int n_in,
                              void* d_out, int out_size)
{
    const float* query = (const float*)d_in[0];
    const float* key   = (const float*)d_in[1];
    const float* value = (const float*)d_in[2];
    // d_in[3] rewards, d_in[4] mask: mathematically no-ops
    const float* Wq = (const float*)d_in[5];
    const float* bq = (const float*)d_in[6];
    const float* Wk = (const float*)d_in[7];
    const float* bk = (const float*)d_in[8];
    const float* Wv = (const float*)d_in[9];
    const float* bv = (const float*)d_in[10];
    const float* Wo = (const float*)d_in[11];
    const float* bo = (const float*)d_in[12];
    float* out = (float*)d_out;

    float *pV;
    cudaGetSymbolAddress((void**)&pV, g_V);
    __half *fA, *fW, *fQ, *fK, *fVt;
    cudaGetSymbolAddress((void**)&fA, g_fA);
    cudaGetSymbolAddress((void**)&fW, g_fW);
    cudaGetSymbolAddress((void**)&fQ, g_fQ);
    cudaGetSymbolAddress((void**)&fK, g_fK);
    cudaGetSymbolAddress((void**)&fVt, g_fVt);

    cudaFuncSetAttribute(gemm_f16,        cudaFuncAttributeMaxDynamicSharedMemorySize, GSM2);
    cudaFuncSetAttribute(attn_scores_mma, cudaFuncAttributeMaxDynamicSharedMemorySize, GSM2);
    cudaFuncSetAttribute(attn_av_mma,     cudaFuncAttributeMaxDynamicSharedMemorySize, AVS);

    const int NA4 = MROWS * HID / 4;
    dim3 tw(HID / 32, HID / 32), tb(32, 8);
    dim3 gg(HID / 128, MROWS / 128);   // (16, 32)

    // Q projection -> fp16
    cvt_f16<<<NA4 / 256, 256>>>(query, fA, NA4);
    transpose_f16<<<tw, tb>>>(Wq, fW, HID, HID);
    gemm_f16<<<gg, 256, GSM2>>>(fA, fW, bq, nullptr, fQ);
    // K projection -> fp16
    cvt_f16<<<NA4 / 256, 256>>>(key, fA, NA4);
    transpose_f16<<<tw, tb>>>(Wk, fW, HID, HID);
    gemm_f16<<<gg, 256, GSM2>>>(fA, fW, bk, nullptr, fK);
    // V projection -> fp32, then transpose to fp16
    cvt_f16<<<NA4 / 256, 256>>>(value, fA, NA4);
    transpose_f16<<<tw, tb>>>(Wv, fW, HID, HID);
    gemm_f16<<<gg, 256, GSM2>>>(fA, fW, bv, pV, nullptr);
    transpose_f16<<<dim3(HID / 32, MROWS / 32), tb>>>(pV, fVt, HID, MROWS);

    // attention
    attn_scores_mma<<<dim3(S / 128, S / 128, BATCH * NH), 256, GSM2>>>();
    combine_stats<<<(BATCH * NH * S) / 256, 256>>>();
    attn_av_mma<<<dim3(S / 128, BATCH, NH), 256, AVS>>>();

    if (out_size >= 2 * MROWS * HID) {
        mean_attn<<<(BATCH * S * S / 4) / 256, 256>>>(out + (size_t)MROWS * HID);
    }

    // O projection (attended already fp16 in g_fA)
    transpose_f16<<<tw, tb>>>(Wo, fW, HID, HID);
    gemm_f16<<<gg, 256, GSM2>>>(fA, fW, bo, out, nullptr);
}

// round 14
// speedup vs baseline: 2.5927x; 1.1296x over previous
#include <cuda_runtime.h>
#include <cuda_fp16.h>
#include <cstdint>

#define S 2048
#define HID 2048
#define NH 16
#define HD 128
#define BATCH 2
#define MROWS (BATCH*S)   // 4096

typedef unsigned long long ull;

// ---------------- scratch (static device allocations; no cudaMalloc) --------
__device__ float  g_V [(size_t)MROWS*HID];
__device__ __half g_Sh[(size_t)BATCH*NH*S*S];  // raw scaled scores, fp16 (268 MB)
__device__ float  g_m [BATCH*NH*S];
__device__ float  g_li[BATCH*NH*S];
__device__ float  g_pm[(size_t)BATCH*NH*S*16]; // per-(row, ktile) partial max
__device__ float  g_pl[(size_t)BATCH*NH*S*16]; // per-(row, ktile) partial sumexp

__device__ __half g_fA [(size_t)MROWS*HID];    // GEMM A operand / attended
__device__ __half g_fW [(size_t)HID*HID];      // weight, transposed [N,K]
__device__ __half g_fQ [(size_t)MROWS*HID];    // Q projection (fp16)
__device__ __half g_fK [(size_t)MROWS*HID];    // K projection (fp16)
__device__ __half g_fVt[(size_t)HID*MROWS];    // V^T (fp16) [HID x MROWS]

// ======================= PTX helpers =========================================
__device__ __forceinline__ uint32_t smem_u32(const void* p){
    uint32_t a;
    asm("{ .reg .u64 t; cvta.to.shared.u64 t, %1; cvt.u32.u64 %0, t; }" : "=r"(a) : "l"(p));
    return a;
}
#define CP16(sm, gp)  asm volatile("cp.async.cg.shared.global [%0], [%1], 16;" :: "r"(sm), "l"(gp) : "memory")
#define CP_COMMIT()   asm volatile("cp.async.commit_group;" ::: "memory")
#define CP_WAIT1()    asm volatile("cp.async.wait_group 1;" ::: "memory")
#define CP_WAIT0()    asm volatile("cp.async.wait_group 0;" ::: "memory")

#define LDSM4(R, A) asm volatile("ldmatrix.sync.aligned.m8n8.x4.shared.b16 {%0,%1,%2,%3}, [%4];" \
    : "=r"((R)[0]), "=r"((R)[1]), "=r"((R)[2]), "=r"((R)[3]) : "r"(A))

#define MMAF16(D, Af, B0, B1) asm volatile( \
    "mma.sync.aligned.m16n8k16.row.col.f32.f16.f16.f32 " \
    "{%0,%1,%2,%3}, {%4,%5,%6,%7}, {%8,%9}, {%0,%1,%2,%3};" \
    : "+f"((D)[0]), "+f"((D)[1]), "+f"((D)[2]), "+f"((D)[3]) \
    : "r"((Af)[0]), "r"((Af)[1]), "r"((Af)[2]), "r"((Af)[3]), \
      "r"(B0), "r"(B1))

__device__ __forceinline__ uint32_t h2u(float a, float b){
    __half2 h = __floats2half2_rn(a, b);
    return *(uint32_t*)&h;
}

// ======================= prep kernels ========================================
__global__ void __launch_bounds__(256) cvt_f16(
    const float* __restrict__ in, __half* __restrict__ out, int n4)
{
    int i = blockIdx.x * 256 + threadIdx.x;
    if (i >= n4) return;
    float4 v = ((const float4*)in)[i];
    uint32_t a = h2u(v.x, v.y), b = h2u(v.z, v.w);
    ((uint2*)out)[i] = make_uint2(a, b);
}

// in [RI x CI] fp32 -> out [CI x RI] fp16 (transpose)
__global__ void __launch_bounds__(256) transpose_f16(
    const float* __restrict__ in, __half* __restrict__ out, int CI, int RI)
{
    __shared__ float ts[32][33];
    int tx = threadIdx.x, ty = threadIdx.y;          // block (32,8)
    int n0 = blockIdx.x * 32, k0 = blockIdx.y * 32;
#pragma unroll
    for (int j = 0; j < 4; j++)
        ts[ty + j * 8][tx] = in[(size_t)(k0 + ty + j * 8) * CI + n0 + tx];
    __syncthreads();
#pragma unroll
    for (int j = 0; j < 4; j++)
        out[(size_t)(n0 + ty + j * 8) * RI + k0 + tx] = __float2half(ts[tx][ty + j * 8]);
}

// ======================= fp16 HMMA GEMM: C = A@W + bias ======================
#define BK 32
#define NKCH (HID/BK)                 // 64
#define SSTR 40                       // fp16 per smem row (pad 32->40)
#define MATB (128*SSTR*2)             // 10240 B per matrix tile
#define STG2 (2*MATB)                 // A + B: 20480 B
#define GSM2 (2*STG2)                 // 40960 B
#define AVS  (GSM2 + 1024)

__global__ void __launch_bounds__(256) gemm_f16(
    const __half* __restrict__ A, const __half* __restrict__ B,
    const float* __restrict__ bias, float* __restrict__ C,
    __half* __restrict__ Cf)
{
    extern __shared__ __align__(128) char smg[];
    uint32_t sb = smem_u32(smg);
    int tid = threadIdx.x, lane = tid & 31, wid = tid >> 5;
    int brow = blockIdx.y * 128, bcol = blockIdx.x * 128;
    int wm = (wid >> 1) * 32, wn = (wid & 1) * 64;

    int lr = tid >> 2, lc = (tid & 3) * 8;
    const __half* srcA0 = A + (size_t)(brow + lr) * HID + lc;
    const __half* srcA1 = A + (size_t)(brow + lr + 64) * HID + lc;
    const __half* srcB0 = B + (size_t)(bcol + lr) * HID + lc;
    const __half* srcB1 = B + (size_t)(bcol + lr + 64) * HID + lc;
    uint32_t d0 = (uint32_t)(lr * SSTR + lc) * 2;
    uint32_t d1 = (uint32_t)((lr + 64) * SSTR + lc) * 2;

#define LOAD_CHUNK(kk, st) do { \
    uint32_t bb = sb + (uint32_t)(st) * STG2; \
    int k0 = (kk) * BK; \
    CP16(bb + d0, srcA0 + k0); CP16(bb + d1, srcA1 + k0); \
    CP16(bb + MATB + d0, srcB0 + k0); CP16(bb + MATB + d1, srcB1 + k0); \
    CP_COMMIT(); } while (0)

    uint32_t a_off = (uint32_t)((wm + (lane & 15)) * SSTR + ((lane >> 1) & 8)) * 2;
    uint32_t b4_off = (uint32_t)((wn + (lane & 7) + ((lane >> 4) << 3)) * SSTR + (lane & 8)) * 2;

    float acc[2][8][4];
#pragma unroll
    for (int mt = 0; mt < 2; mt++)
#pragma unroll
        for (int nt = 0; nt < 8; nt++)
#pragma unroll
            for (int j = 0; j < 4; j++) acc[mt][nt][j] = 0.0f;

    LOAD_CHUNK(0, 0);
    LOAD_CHUNK(1, 1);

    for (int k = 0; k < NKCH; k++) {
        if (k < NKCH - 2) { CP_WAIT1(); } else { CP_WAIT0(); }
        __syncthreads();
        uint32_t stb = sb + (uint32_t)(k & 1) * STG2;
#pragma unroll
        for (int kst = 0; kst < 2; kst++) {
            uint32_t kb = (uint32_t)kst * 32;
            uint32_t a[2][4], b4[4][4];
            LDSM4(a[0], stb + a_off + kb);
            LDSM4(a[1], stb + a_off + kb + 16*SSTR*2);
#pragma unroll
            for (int g = 0; g < 4; g++)
                LDSM4(b4[g], stb + MATB + b4_off + kb + g*16*SSTR*2);
#pragma unroll
            for (int mt = 0; mt < 2; mt++)
#pragma unroll
                for (int g = 0; g < 4; g++) {
                    MMAF16(acc[mt][2*g],   a[mt], b4[g][0], b4[g][1]);
                    MMAF16(acc[mt][2*g+1], a[mt], b4[g][2], b4[g][3]);
                }
        }
        __syncthreads();
        if (k + 2 < NKCH) LOAD_CHUNK(k + 2, k & 1);
    }
#undef LOAD_CHUNK

    int gid = lane >> 2, tig = lane & 3;
#pragma unroll
    for (int mt = 0; mt < 2; mt++) {
        int m0 = brow + wm + mt * 16 + gid;
#pragma unroll
        for (int nt = 0; nt < 8; nt++) {
            int n0 = bcol + wn + nt * 8 + tig * 2;
            float2 bb = *(const float2*)(bias + n0);
            float v0 = acc[mt][nt][0] + bb.x, v1 = acc[mt][nt][1] + bb.y;
            float v2 = acc[mt][nt][2] + bb.x, v3 = acc[mt][nt][3] + bb.y;
            if (Cf) {
                *(uint32_t*)(Cf + (size_t)m0 * HID + n0)     = h2u(v0, v1);
                *(uint32_t*)(Cf + (size_t)(m0+8) * HID + n0) = h2u(v2, v3);
            } else {
                *(float2*)(C + (size_t)m0 * HID + n0)     = make_float2(v0, v1);
                *(float2*)(C + (size_t)(m0+8) * HID + n0) = make_float2(v2, v3);
            }
        }
    }
}

// ================ attention scores: S = scale * Q @ K^T (fp16 HMMA) =========
#define SNK (HD/BK)   // 4
__global__ void __launch_bounds__(256) attn_scores_mma()
{
    extern __shared__ __align__(128) char smg[];
    uint32_t sb = smem_u32(smg);
    int tid = threadIdx.x, lane = tid & 31, wid = tid >> 5;
    int kt = blockIdx.x, qt = blockIdx.y, bh = blockIdx.z;
    int b = bh >> 4, h = bh & 15;
    int wm = (wid >> 1) * 32, wn = (wid & 1) * 64;

    int lr = tid >> 2, lc = (tid & 3) * 8;
    const __half* srcA0 = g_fQ + (size_t)(b*S + qt*128 + lr) * HID + h*HD + lc;
    const __half* srcA1 = srcA0 + (size_t)64 * HID;
    const __half* srcB0 = g_fK + (size_t)(b*S + kt*128 + lr) * HID + h*HD + lc;
    const __half* srcB1 = srcB0 + (size_t)64 * HID;
    uint32_t d0 = (uint32_t)(lr * SSTR + lc) * 2;
    uint32_t d1 = (uint32_t)((lr + 64) * SSTR + lc) * 2;

#define LOAD_CHUNK(kk, st) do { \
    uint32_t bb = sb + (uint32_t)(st) * STG2; \
    int k0 = (kk) * BK; \
    CP16(bb + d0, srcA0 + k0); CP16(bb + d1, srcA1 + k0); \
    CP16(bb + MATB + d0, srcB0 + k0); CP16(bb + MATB + d1, srcB1 + k0); \
    CP_COMMIT(); } while (0)

    uint32_t a_off  = (uint32_t)((wm + (lane & 15)) * SSTR + ((lane >> 1) & 8)) * 2;
    uint32_t b4_off = (uint32_t)((wn + (lane & 7) + ((lane >> 4) << 3)) * SSTR + (lane & 8)) * 2;

    float acc[2][8][4];
#pragma unroll
    for (int mt = 0; mt < 2; mt++)
#pragma unroll
        for (int nt = 0; nt < 8; nt++)
#pragma unroll
            for (int j = 0; j < 4; j++) acc[mt][nt][j] = 0.0f;

    LOAD_CHUNK(0, 0);
    LOAD_CHUNK(1, 1);

    for (int k = 0; k < SNK; k++) {
        if (k < SNK - 2) { CP_WAIT1(); } else { CP_WAIT0(); }
        __syncthreads();
        uint32_t stb = sb + (uint32_t)(k & 1) * STG2;
#pragma unroll
        for (int kst = 0; kst < 2; kst++) {
            uint32_t kb = (uint32_t)kst * 32;
            uint32_t a[2][4], b4[4][4];
            LDSM4(a[0], stb + a_off + kb);
            LDSM4(a[1], stb + a_off + kb + 16*SSTR*2);
#pragma unroll
            for (int g = 0; g < 4; g++)
                LDSM4(b4[g], stb + MATB + b4_off + kb + g*16*SSTR*2);
#pragma unroll
            for (int mt = 0; mt < 2; mt++)
#pragma unroll
                for (int g = 0; g < 4; g++) {
                    MMAF16(acc[mt][2*g],   a[mt], b4[g][0], b4[g][1]);
                    MMAF16(acc[mt][2*g+1], a[mt], b4[g][2], b4[g][3]);
                }
        }
        __syncthreads();
        if (k + 2 < SNK) LOAD_CHUNK(k + 2, k & 1);
    }
#undef LOAD_CHUNK

    const float scale = 0.08838834764831843f;   // 1/sqrt(128)
#pragma unroll
    for (int mt = 0; mt < 2; mt++)
#pragma unroll
        for (int nt = 0; nt < 8; nt++)
#pragma unroll
            for (int j = 0; j < 4; j++) acc[mt][nt][j] *= scale;

    // store scaled scores as fp16
    int gid = lane >> 2, tig = lane & 3;
    size_t srow0 = (size_t)bh * S + (size_t)qt * 128;
#pragma unroll
    for (int mt = 0; mt < 2; mt++) {
        size_t m0 = srow0 + wm + mt * 16 + gid;
#pragma unroll
        for (int nt = 0; nt < 8; nt++) {
            int n0 = kt * 128 + wn + nt * 8 + tig * 2;
            *(uint32_t*)&g_Sh[m0 * S + n0]       = h2u(acc[mt][nt][0], acc[mt][nt][1]);
            *(uint32_t*)&g_Sh[(m0 + 8) * S + n0] = h2u(acc[mt][nt][2], acc[mt][nt][3]);
        }
    }

    __syncthreads();
    float* sm = (float*)smg;          // [2][128]
    float* sl = sm + 256;             // [2][128]
#pragma unroll
    for (int mt = 0; mt < 2; mt++) {
#pragma unroll
        for (int half = 0; half < 2; half++) {
            float mx = -1e30f;
#pragma unroll
            for (int nt = 0; nt < 8; nt++)
                mx = fmaxf(mx, fmaxf(acc[mt][nt][half*2], acc[mt][nt][half*2+1]));
            mx = fmaxf(mx, __shfl_xor_sync(0xffffffffu, mx, 1));
            mx = fmaxf(mx, __shfl_xor_sync(0xffffffffu, mx, 2));
            float se = 0.0f;
#pragma unroll
            for (int nt = 0; nt < 8; nt++)
                se += __expf(acc[mt][nt][half*2] - mx) + __expf(acc[mt][nt][half*2+1] - mx);
            se += __shfl_xor_sync(0xffffffffu, se, 1);
            se += __shfl_xor_sync(0xffffffffu, se, 2);
            if (tig == 0) {
                int r = wm + mt * 16 + half * 8 + gid;
                sm[(wid & 1) * 128 + r] = mx;
                sl[(wid & 1) * 128 + r] = se;
            }
        }
    }
    __syncthreads();
    if (tid < 128) {
        float m0 = sm[tid], m1 = sm[128 + tid];
        float l0 = sl[tid], l1 = sl[128 + tid];
        float M = fmaxf(m0, m1);
        float L = l0 * __expf(m0 - M) + l1 * __expf(m1 - M);
        size_t q = (size_t)bh * S + (size_t)qt * 128 + tid;
        g_pm[q * 16 + kt] = M;
        g_pl[q * 16 + kt] = L;
    }
}

// ================ combine partial stats -> m, 1/l ============================
__global__ void __launch_bounds__(256) combine_stats()
{
    int r = blockIdx.x * 256 + threadIdx.x;     // 0..65535
    float M = -1e30f;
#pragma unroll
    for (int i = 0; i < 16; i++) M = fmaxf(M, g_pm[(size_t)r * 16 + i]);
    float L = 0.0f;
#pragma unroll
    for (int i = 0; i < 16; i++)
        L += g_pl[(size_t)r * 16 + i] * __expf(g_pm[(size_t)r * 16 + i] - M);
    g_m[r]  = M;
    g_li[r] = 1.0f / L;
}

// ================ attn AV: attended = softmax(S) @ V (fp16 HMMA) =============
__global__ void __launch_bounds__(256) attn_av_mma()
{
    extern __shared__ __align__(128) char smg[];
    uint32_t sb = smem_u32(smg);
    float* msh = (float*)(smg + GSM2);         // [128]
    float* lih = msh + 128;                    // [128]
    int tid = threadIdx.x, lane = tid & 31, wid = tid >> 5;
    int qt = blockIdx.x, b = blockIdx.y, h = blockIdx.z;
    int bh = b * NH + h;
    int wm = (wid >> 1) * 32, wn = (wid & 1) * 64;

    if (tid < 128) {
        size_t q = (size_t)bh * S + (size_t)qt * 128 + tid;
        msh[tid] = g_m[q];
        lih[tid] = g_li[q];
    }
    __syncthreads();

    int pr = tid >> 1, pc = (tid & 1) * 16;
    const __half* srcP = g_Sh + ((size_t)bh * S + (size_t)qt * 128 + pr) * S + pc;
    float pm_r = msh[pr], pli_r = lih[pr];
    uint32_t pdst = (uint32_t)(pr * SSTR + pc) * 2;

    int lr = tid >> 2, lc = (tid & 3) * 8;
    const __half* srcV0 = g_fVt + (size_t)(h*HD + lr) * MROWS + b*S + lc;
    const __half* srcV1 = srcV0 + (size_t)64 * MROWS;
    uint32_t d0 = (uint32_t)(lr * SSTR + lc) * 2;
    uint32_t d1 = (uint32_t)((lr + 64) * SSTR + lc) * 2;

#define LOADV(kk, st) do { \
    uint32_t bb = sb + (uint32_t)(st) * STG2; \
    int k0 = (kk) * BK; \
    CP16(bb + MATB + d0, srcV0 + k0); CP16(bb + MATB + d1, srcV1 + k0); \
    CP_COMMIT(); } while (0)

// read fp16 scores, convert to p (fp16) into smem P tile
#define CONVP(kk, st) do { \
    uint32_t bb = sb + (uint32_t)(st) * STG2; \
    int k0 = (kk) * BK; \
    _Pragma("unroll") \
    for (int j = 0; j < 2; j++) { \
        uint4 u = *(const uint4*)(srcP + k0 + j * 8); \
        float2 f0 = __half22float2(*(__half2*)&u.x); \
        float2 f1 = __half22float2(*(__half2*)&u.y); \
        float2 f2 = __half22float2(*(__half2*)&u.z); \
        float2 f3 = __half22float2(*(__half2*)&u.w); \
        uint32_t o0 = h2u(__expf(f0.x - pm_r) * pli_r, __expf(f0.y - pm_r) * pli_r); \
        uint32_t o1 = h2u(__expf(f1.x - pm_r) * pli_r, __expf(f1.y - pm_r) * pli_r); \
        uint32_t o2 = h2u(__expf(f2.x - pm_r) * pli_r, __expf(f2.y - pm_r) * pli_r); \
        uint32_t o3 = h2u(__expf(f3.x - pm_r) * pli_r, __expf(f3.y - pm_r) * pli_r); \
        asm volatile("st.shared.v4.b32 [%0], {%1, %2, %3, %4};" \
            :: "r"(bb + pdst + (uint32_t)j * 16), "r"(o0), "r"(o1), "r"(o2), "r"(o3)); \
    } } while (0)

    uint32_t a_off  = (uint32_t)((wm + (lane & 15)) * SSTR + ((lane >> 1) & 8)) * 2;
    uint32_t b4_off = (uint32_t)((wn + (lane & 7) + ((lane >> 4) << 3)) * SSTR + (lane & 8)) * 2;

    float acc[2][8][4];
#pragma unroll
    for (int mt = 0; mt < 2; mt++)
#pragma unroll
        for (int nt = 0; nt < 8; nt++)
#pragma unroll
            for (int j = 0; j < 4; j++) acc[mt][nt][j] = 0.0f;

    LOADV(0, 0);
    LOADV(1, 1);

    for (int k = 0; k < NKCH; k++) {        // 64 chunks of 32 seq positions
        if (k < NKCH - 2) { CP_WAIT1(); } else { CP_WAIT0(); }
        CONVP(k, k & 1);
        __syncthreads();
        uint32_t stb = sb + (uint32_t)(k & 1) * STG2;
#pragma unroll
        for (int kst = 0; kst < 2; kst++) {
            uint32_t kb = (uint32_t)kst * 32;
            uint32_t a[2][4], b4[4][4];
            LDSM4(a[0], stb + a_off + kb);
            LDSM4(a[1], stb + a_off + kb + 16*SSTR*2);
#pragma unroll
            for (int g = 0; g < 4; g++)
                LDSM4(b4[g], stb + MATB + b4_off + kb + g*16*SSTR*2);
#pragma unroll
            for (int mt = 0; mt < 2; mt++)
#pragma unroll
                for (int g = 0; g < 4; g++) {
                    MMAF16(acc[mt][2*g],   a[mt], b4[g][0], b4[g][1]);
                    MMAF16(acc[mt][2*g+1], a[mt], b4[g][2], b4[g][3]);
                }
        }
        __syncthreads();
        if (k + 2 < NKCH) LOADV(k + 2, k & 1);
    }
#undef LOADV
#undef CONVP

    int gid = lane >> 2, tig = lane & 3;
#pragma unroll
    for (int mt = 0; mt < 2; mt++) {
        size_t m0 = (size_t)(b * S + qt * 128 + wm + mt * 16 + gid);
#pragma unroll
        for (int nt = 0; nt < 8; nt++) {
            int n0 = h * HD + wn + nt * 8 + tig * 2;
            *(uint32_t*)(g_fA + m0 * HID + n0) =
                h2u(acc[mt][nt][0], acc[mt][nt][1]);
            *(uint32_t*)(g_fA + (m0+8) * HID + n0) =
                h2u(acc[mt][nt][2], acc[mt][nt][3]);
        }
    }
}

// ---------------- head-mean of attention weights (fp16 scores -> exp) -------
__global__ void __launch_bounds__(256) mean_attn(float* __restrict__ out2)
{
    int f = blockIdx.x * 256 + threadIdx.x;
    int b  = f >> 20;
    int r  = f & 1048575;
    int q  = r >> 9;
    int k4 = (r & 511) * 4;
    float mm[NH], ll[NH];
#pragma unroll
    for (int h = 0; h < NH; h++) {
        int bh = b * NH + h;
        mm[h] = g_m[bh * S + q];
        ll[h] = g_li[bh * S + q];
    }
    float4 acc = make_float4(0.f, 0.f, 0.f, 0.f);
#pragma unroll
    for (int h = 0; h < NH; h++) {
        size_t base = ((size_t)(b * NH + h) * S + q) * S + k4;
        uint2 u = *(const uint2*)&g_Sh[base];
        float2 f0 = __half22float2(*(__half2*)&u.x);
        float2 f1 = __half22float2(*(__half2*)&u.y);
        acc.x += __expf(f0.x - mm[h]) * ll[h];
        acc.y += __expf(f0.y - mm[h]) * ll[h];
        acc.z += __expf(f1.x - mm[h]) * ll[h];
        acc.w += __expf(f1.y - mm[h]) * ll[h];
    }
    const float inv = 1.0f / 16.0f;
    acc.x *= inv; acc.y *= inv; acc.z *= inv; acc.w *= inv;
    *(float4*)&out2[(size_t)f * 4] = acc;
}

// ---------------- launch ----------------------------------------------------
extern "C" void kernel_launch(void* const* d_in, const int* in_sizes, int n_in,
                              void* d_out, int out_size)
{
    const float* query = (const float*)d_in[0];
    const float* key   = (const float*)d_in[1];
    const float* value = (const float*)d_in[2];
    // d_in[3] rewards, d_in[4] mask: mathematically no-ops
    const float* Wq = (const float*)d_in[5];
    const float* bq = (const float*)d_in[6];
    const float* Wk = (const float*)d_in[7];
    const float* bk = (const float*)d_in[8];
    const float* Wv = (const float*)d_in[9];
    const float* bv = (const float*)d_in[10];
    const float* Wo = (const float*)d_in[11];
    const float* bo = (const float*)d_in[12];
    float* out = (float*)d_out;

    float *pV;
    cudaGetSymbolAddress((void**)&pV, g_V);
    __half *fA, *fW, *fQ, *fK, *fVt;
    cudaGetSymbolAddress((void**)&fA, g_fA);
    cudaGetSymbolAddress((void**)&fW, g_fW);
    cudaGetSymbolAddress((void**)&fQ, g_fQ);
    cudaGetSymbolAddress((void**)&fK, g_fK);
    cudaGetSymbolAddress((void**)&fVt, g_fVt);

    cudaFuncSetAttribute(gemm_f16,        cudaFuncAttributeMaxDynamicSharedMemorySize, GSM2);
    cudaFuncSetAttribute(attn_scores_mma, cudaFuncAttributeMaxDynamicSharedMemorySize, GSM2);
    cudaFuncSetAttribute(attn_av_mma,     cudaFuncAttributeMaxDynamicSharedMemorySize, AVS);

    const int NA4 = MROWS * HID / 4;
    dim3 tw(HID / 32, HID / 32), tb(32, 8);
    dim3 gg(HID / 128, MROWS / 128);   // (16, 32)

    // Q projection -> fp16
    cvt_f16<<<NA4 / 256, 256>>>(query, fA, NA4);
    transpose_f16<<<tw, tb>>>(Wq, fW, HID, HID);
    gemm_f16<<<gg, 256, GSM2>>>(fA, fW, bq, nullptr, fQ);
    // K projection -> fp16
    cvt_f16<<<NA4 / 256, 256>>>(key, fA, NA4);
    transpose_f16<<<tw, tb>>>(Wk, fW, HID, HID);
    gemm_f16<<<gg, 256, GSM2>>>(fA, fW, bk, nullptr, fK);
    // V projection -> fp32, then transpose to fp16
    cvt_f16<<<NA4 / 256, 256>>>(value, fA, NA4);
    transpose_f16<<<tw, tb>>>(Wv, fW, HID, HID);
    gemm_f16<<<gg, 256, GSM2>>>(fA, fW, bv, pV, nullptr);
    transpose_f16<<<dim3(HID / 32, MROWS / 32), tb>>>(pV, fVt, HID, MROWS);

    // attention
    attn_scores_mma<<<dim3(S / 128, S / 128, BATCH * NH), 256, GSM2>>>();
    combine_stats<<<(BATCH * NH * S) / 256, 256>>>();
    attn_av_mma<<<dim3(S / 128, BATCH, NH), 256, AVS>>>();

    if (out_size >= 2 * MROWS * HID) {
        mean_attn<<<(BATCH * S * S / 4) / 256, 256>>>(out + (size_t)MROWS * HID);
    }

    // O projection (attended already fp16 in g_fA)
    transpose_f16<<<tw, tb>>>(Wo, fW, HID, HID);
    gemm_f16<<<gg, 256, GSM2>>>(fA, fW, bo, out, nullptr);
}